// round 14
// baseline (speedup 1.0000x reference)
#include <cuda_runtime.h>
#include <cuda_fp16.h>
#include <cstdint>

// FlashAttention B=4,H=12,S=4096,D=64, TILE=128, fp32 in/out.
// mma.sync m16n8k16 fp16 (plain sm_103 target — tcgen05 unavailable).
// Reference recurrence kept exactly: p = exp(s + mx - 2*nm),
// O = O*exp(m-nm) + P@V, ssum = ssum*exp(m-nm) + rowsum(P).
// Base-2 softmax domain (Q pre-scaled by 0.125*log2 e).
//
// R14: deferred-MMA2 software pipeline. At iter kt the warp issues
// MMA2(kt-1) manually interleaved with softmax(kt) (independent chains),
// so each warp self-hides its softmax latency under tensor work.
// pl/ph double-buffered in registers (parity-unrolled loop), V triple-
// buffered in smem, o-rescale by osc(kt) moved after MMA2(kt-1) —
// arithmetic chain identical to the reference schedule.

#define S_LEN 4096
#define NKT   32
#define BH_N  48

#define TILEB 16384
#define QOFF  0                       // 64 rows x 128B = 8KB (fp16 Q)
#define KOFF  8192                    // K: 2 x 16KB
#define VOFF  (8192 + 2*16384)        // V: 3 x 16KB
#define VBUF2 (VOFF + 2*16384)        // Q fp32 staging pre-loop
#define SMEM_MAIN (VOFF + 3*16384)    // 90112

#define QSCALE (0.125f * 1.44269504f)

__device__ __align__(128) __half g_Kh[(size_t)BH_N * S_LEN * 64];
__device__ __align__(128) __half g_Vh[(size_t)BH_N * S_LEN * 64];

// ---------------- pre-kernel: K,V fp32 -> fp16 ------------------------------
__global__ void __launch_bounds__(256) cvt_pre(const float4* __restrict__ K,
                                               const float4* __restrict__ V)
{
    const int PER = (int)((size_t)BH_N * S_LEN * 64 / 4);
    int gid = blockIdx.x * 256 + threadIdx.x;
    int stride = gridDim.x * 256;
    for (int i = gid; i < 2 * PER; i += stride) {
        int t = i / PER, off = i - t * PER;
        const float4* src = (t == 0) ? K : V;
        uint2* dst = (uint2*)((t == 0) ? g_Kh : g_Vh);
        float4 v = src[off];
        __half2 h0 = __floats2half2_rn(v.x, v.y);
        __half2 h1 = __floats2half2_rn(v.z, v.w);
        uint2 w;
        w.x = *(uint32_t*)&h0;
        w.y = *(uint32_t*)&h1;
        dst[off] = w;
    }
}

// ---------------- helpers ----------------
__device__ __forceinline__ uint32_t smem_u32(const void* p){
    uint32_t a; asm("{ .reg .u64 t; cvta.to.shared.u64 t, %1; cvt.u32.u64 %0, t; }"
                    : "=r"(a) : "l"(p)); return a;
}
__device__ __forceinline__ void cpa16(uint32_t dst, const void* src){
    asm volatile("cp.async.cg.shared.global [%0], [%1], 16;" :: "r"(dst), "l"(src));
}
__device__ __forceinline__ void ldsm4(uint32_t& r0, uint32_t& r1, uint32_t& r2,
                                      uint32_t& r3, uint32_t a){
    asm volatile("ldmatrix.sync.aligned.m8n8.x4.shared.b16 {%0,%1,%2,%3}, [%4];"
                 : "=r"(r0), "=r"(r1), "=r"(r2), "=r"(r3) : "r"(a));
}
__device__ __forceinline__ void ldsm4t(uint32_t& r0, uint32_t& r1, uint32_t& r2,
                                       uint32_t& r3, uint32_t a){
    asm volatile("ldmatrix.sync.aligned.m8n8.x4.trans.shared.b16 {%0,%1,%2,%3}, [%4];"
                 : "=r"(r0), "=r"(r1), "=r"(r2), "=r"(r3) : "r"(a));
}
__device__ __forceinline__ void mma168(float* d, const uint32_t* a,
                                       uint32_t b0, uint32_t b1){
    asm volatile(
        "mma.sync.aligned.m16n8k16.row.col.f32.f16.f16.f32 "
        "{%0,%1,%2,%3}, {%4,%5,%6,%7}, {%8,%9}, {%0,%1,%2,%3};"
        : "+f"(d[0]), "+f"(d[1]), "+f"(d[2]), "+f"(d[3])
        : "r"(a[0]), "r"(a[1]), "r"(a[2]), "r"(a[3]), "r"(b0), "r"(b1));
}
__device__ __forceinline__ void mma168_z(float* d, const uint32_t* a,
                                         uint32_t b0, uint32_t b1){
    asm volatile(
        "mma.sync.aligned.m16n8k16.row.col.f32.f16.f16.f32 "
        "{%0,%1,%2,%3}, {%4,%5,%6,%7}, {%8,%9}, {%10,%10,%10,%10};"
        : "=f"(d[0]), "=f"(d[1]), "=f"(d[2]), "=f"(d[3])
        : "r"(a[0]), "r"(a[1]), "r"(a[2]), "r"(a[3]), "r"(b0), "r"(b1),
          "f"(0.0f));
}
__device__ __forceinline__ uint32_t exp2_h2(float lo, float hi, float adj){
    __half2 h = __floats2half2_rn(lo + adj, hi + adj);
    h = h2exp2(h);
    return *(uint32_t*)&h;
}

// stage one K tile + one V tile (fp16, 16KB each); separate buffer indices
__device__ __forceinline__ void stage_kv(uint32_t sb, int kbuf, int vbuf, int tid,
                                         const __half* gk, const __half* gv){
    const int row0 = tid >> 3, c = tid & 7;
    const uint32_t sw = (uint32_t)((c ^ (row0 & 7)) << 4);
    uint32_t dk = sb + KOFF + kbuf * TILEB + row0 * 128 + sw;
    uint32_t dv = sb + VOFF + vbuf * TILEB + row0 * 128 + sw;
    const __half* sk = gk + row0 * 64 + c * 8;
    const __half* sv = gv + row0 * 64 + c * 8;
    #pragma unroll
    for (int i = 0; i < 8; i++){
        cpa16(dk, sk); dk += 2048; sk += 1024;
        cpa16(dv, sv); dv += 2048; sv += 1024;
    }
    asm volatile("cp.async.commit_group;" ::: "memory");
}

// one n-strip of deferred MMA2 (8 D-tile HMMA + rowsum HMMA)
__device__ __forceinline__ void mma2_kk(float (&o)[9][4], uint32_t vrow_kk,
                                        const uint32_t (&ckV)[4], uint32_t bone,
                                        uint32_t a0, uint32_t a1,
                                        uint32_t a2, uint32_t a3){
    uint32_t aA[4] = { a0, a1, a2, a3 };
    uint32_t b0, b1, b2, b3;
    ldsm4t(b0, b1, b2, b3, vrow_kk + ckV[0]);
    mma168(o[0], aA, b0, b1); mma168(o[1], aA, b2, b3);
    ldsm4t(b0, b1, b2, b3, vrow_kk + ckV[1]);
    mma168(o[2], aA, b0, b1); mma168(o[3], aA, b2, b3);
    ldsm4t(b0, b1, b2, b3, vrow_kk + ckV[2]);
    mma168(o[4], aA, b0, b1); mma168(o[5], aA, b2, b3);
    ldsm4t(b0, b1, b2, b3, vrow_kk + ckV[3]);
    mma168(o[6], aA, b0, b1); mma168(o[7], aA, b2, b3);
    mma168(o[8], aA, bone, bone);
}

// one pipelined iteration (kt >= 1): MMA1(kt); MMA2(kt-1) interleaved with
// softmax(kt); o-rescale by osc(kt) after MMA2(kt-1).
__device__ __forceinline__ void fa_iter(
    int kt, uint32_t sb, int tid,
    const __half* gk, const __half* gv,
    const uint32_t (&qA)[4][4], const uint32_t (&ckK)[4], const uint32_t (&ckV)[4],
    int rbK, int rbV, uint32_t bone,
    float (&o)[9][4], float &m1, float &m2,
    const uint32_t (&plP)[16], const uint32_t (&phP)[16],
    uint32_t (&plC)[16], uint32_t (&phC)[16])
{
    if (kt + 1 < NKT)
        stage_kv(sb, (kt + 1) & 1, (kt + 1) % 3, tid,
                 gk + (size_t)(kt + 1) * 8192, gv + (size_t)(kt + 1) * 8192);

    // ---- MMA1(kt) + fused partial row-max ----
    float acc[16][4];
    float mx1 = -INFINITY, mx2 = -INFINITY;
    {
        uint32_t krow = sb + KOFF + (kt & 1) * TILEB + rbK * 128;
        #pragma unroll
        for (int j4 = 0; j4 < 8; j4++){
            {
                uint32_t b0, b1, b2, b3;
                ldsm4(b0, b1, b2, b3, krow + ckK[0]);
                mma168_z(acc[2 * j4],     qA[0], b0, b1);
                mma168_z(acc[2 * j4 + 1], qA[0], b2, b3);
            }
            #pragma unroll
            for (int k = 1; k < 4; k++){
                uint32_t b0, b1, b2, b3;
                ldsm4(b0, b1, b2, b3, krow + ckK[k]);
                mma168(acc[2 * j4],     qA[k], b0, b1);
                mma168(acc[2 * j4 + 1], qA[k], b2, b3);
            }
            krow += 2048;
            mx1 = fmaxf(mx1, fmaxf(fmaxf(acc[2*j4][0], acc[2*j4][1]),
                                   fmaxf(acc[2*j4+1][0], acc[2*j4+1][1])));
            mx2 = fmaxf(mx2, fmaxf(fmaxf(acc[2*j4][2], acc[2*j4][3]),
                                   fmaxf(acc[2*j4+1][2], acc[2*j4+1][3])));
        }
    }

    // ---- interleave: MMA2(kt-1) strips between softmax(kt) steps ----
    const uint32_t vrow = sb + VOFF + ((kt + 2) % 3) * TILEB + rbV * 128;

    mma2_kk(o, vrow,          ckV, bone, plP[0], phP[0], plP[1], phP[1]);
    mx1 = fmaxf(mx1, __shfl_xor_sync(0xffffffffu, mx1, 1));
    mx1 = fmaxf(mx1, __shfl_xor_sync(0xffffffffu, mx1, 2));
    mma2_kk(o, vrow + 2048,   ckV, bone, plP[2], phP[2], plP[3], phP[3]);
    mx2 = fmaxf(mx2, __shfl_xor_sync(0xffffffffu, mx2, 1));
    mx2 = fmaxf(mx2, __shfl_xor_sync(0xffffffffu, mx2, 2));
    mma2_kk(o, vrow + 4096,   ckV, bone, plP[4], phP[4], plP[5], phP[5]);

    const float nm1 = fmaxf(m1, mx1), nm2 = fmaxf(m2, mx2);
    const float adj1 = mx1 - 2.0f * nm1, adj2 = mx2 - 2.0f * nm2;
    const float osc1 = exp2f(m1 - nm1), osc2 = exp2f(m2 - nm2);

    mma2_kk(o, vrow + 6144,   ckV, bone, plP[6], phP[6], plP[7], phP[7]);
    #pragma unroll
    for (int t = 0; t < 4; t++){
        plC[t] = exp2_h2(acc[t][0], acc[t][1], adj1);
        phC[t] = exp2_h2(acc[t][2], acc[t][3], adj2);
    }
    mma2_kk(o, vrow + 8192,   ckV, bone, plP[8], phP[8], plP[9], phP[9]);
    #pragma unroll
    for (int t = 4; t < 8; t++){
        plC[t] = exp2_h2(acc[t][0], acc[t][1], adj1);
        phC[t] = exp2_h2(acc[t][2], acc[t][3], adj2);
    }
    mma2_kk(o, vrow + 10240,  ckV, bone, plP[10], phP[10], plP[11], phP[11]);
    #pragma unroll
    for (int t = 8; t < 12; t++){
        plC[t] = exp2_h2(acc[t][0], acc[t][1], adj1);
        phC[t] = exp2_h2(acc[t][2], acc[t][3], adj2);
    }
    mma2_kk(o, vrow + 12288,  ckV, bone, plP[12], phP[12], plP[13], phP[13]);
    #pragma unroll
    for (int t = 12; t < 16; t++){
        plC[t] = exp2_h2(acc[t][0], acc[t][1], adj1);
        phC[t] = exp2_h2(acc[t][2], acc[t][3], adj2);
    }
    mma2_kk(o, vrow + 14336,  ckV, bone, plP[14], phP[14], plP[15], phP[15]);

    // ---- rescale o by osc(kt) (after MMA2(kt-1), before MMA2(kt)) ----
    if (__any_sync(0xffffffffu, (nm1 != m1) | (nm2 != m2))){
        #pragma unroll
        for (int t = 0; t < 9; t++){
            o[t][0] *= osc1; o[t][1] *= osc1;
            o[t][2] *= osc2; o[t][3] *= osc2;
        }
    }
    m1 = nm1; m2 = nm2;

    asm volatile("cp.async.wait_group 0;" ::: "memory");
    __syncthreads();
}

// ---------------- main kernel: 128 threads, 64 q-rows, 2 CTAs/SM ------------
__global__ void __launch_bounds__(128, 2)
fa_mma(const float* __restrict__ Qf, float* __restrict__ O)
{
    extern __shared__ char smraw[];
    const uint32_t sb = smem_u32(smraw);
    const int tid  = threadIdx.x;
    const int lane = tid & 31;
    const int w    = tid >> 5;
    const int bh   = blockIdx.x >> 6;
    const int qt   = blockIdx.x & 63;

    const float* gqf = Qf + ((size_t)bh * S_LEN + (size_t)qt * 64) * 64;
    const __half* gk = g_Kh + (size_t)bh * S_LEN * 64;
    const __half* gv = g_Vh + (size_t)bh * S_LEN * 64;

    const uint32_t xk = (uint32_t)(lane & 7) << 4;

    // ---- prologue: Q fp32 -> VBUF2 (group 0), K0/V0 (group 1) ----
    {
        uint32_t dq = sb + VBUF2 + tid * 16;
        const float* sq = gqf + tid * 4;
        #pragma unroll
        for (int i = 0; i < 8; i++){ cpa16(dq, sq); dq += 2048; sq += 512; }
        asm volatile("cp.async.commit_group;" ::: "memory");
    }
    stage_kv(sb, 0, 0, tid, gk, gv);
    asm volatile("cp.async.wait_group 1;" ::: "memory");
    __syncthreads();

    // convert Q: smem fp32 -> smem fp16 (scaled, swizzled)
    {
        const int row = tid >> 1, hf = tid & 1;
        const uint32_t srcb = sb + VBUF2 + row * 256 + hf * 128;
        const uint32_t rowbase = sb + QOFF + row * 128;
        #pragma unroll
        for (int i = 0; i < 8; i++){
            uint32_t x0, x1, x2, x3;
            asm volatile("ld.shared.v4.b32 {%0,%1,%2,%3}, [%4];"
                         : "=r"(x0), "=r"(x1), "=r"(x2), "=r"(x3)
                         : "r"(srcb + i * 16));
            __half2 h0 = __floats2half2_rn(__uint_as_float(x0) * QSCALE,
                                           __uint_as_float(x1) * QSCALE);
            __half2 h1 = __floats2half2_rn(__uint_as_float(x2) * QSCALE,
                                           __uint_as_float(x3) * QSCALE);
            int c = hf * 4 + (i >> 1);
            uint32_t a = rowbase + ((uint32_t)(c ^ (row & 7)) << 4) + (i & 1) * 8;
            asm volatile("st.shared.v2.b32 [%0], {%1,%2};"
                         :: "r"(a), "r"(*(uint32_t*)&h0), "r"(*(uint32_t*)&h1));
        }
    }
    asm volatile("cp.async.wait_group 0;" ::: "memory");
    __syncthreads();

    // Q A-fragments (persist)
    uint32_t qA[4][4];
    {
        int qrow = 16 * w + (lane & 15);
        int qc   = lane >> 4;
        uint32_t qb = sb + QOFF + qrow * 128;
        #pragma unroll
        for (int k = 0; k < 4; k++)
            ldsm4(qA[k][0], qA[k][1], qA[k][2], qA[k][3],
                  qb + ((uint32_t)((2 * k + qc) << 4) ^ xk));
    }

    const int rbK = (lane & 7) + ((lane >> 4) << 3);
    const int cbK = (lane >> 3) & 1;
    const int rbV = (lane & 7) + (((lane >> 3) & 1) << 3);
    const int cbV = lane >> 4;
    uint32_t ckK[4], ckV[4];
    #pragma unroll
    for (int k = 0; k < 4; k++){
        ckK[k] = ((uint32_t)((2 * k + cbK) << 4)) ^ xk;
        ckV[k] = ((uint32_t)((2 * k + cbV) << 4)) ^ xk;
    }
    const uint32_t bone = (lane < 4) ? 0x3C003C00u : 0u;

    float o[9][4];
    #pragma unroll
    for (int t = 0; t < 9; t++)
        #pragma unroll
        for (int c = 0; c < 4; c++) o[t][c] = 0.0f;
    float m1 = -INFINITY, m2 = -INFINITY;

    uint32_t plA[16], phA[16], plB[16], phB[16];

    // ---- peel kt = 0: MMA1 + softmax -> plA/phA (no deferred MMA2) ----
    {
        stage_kv(sb, 1, 1, tid, gk + 8192, gv + 8192);

        float acc[16][4];
        float mx1 = -INFINITY, mx2 = -INFINITY;
        {
            uint32_t krow = sb + KOFF + rbK * 128;
            #pragma unroll
            for (int j4 = 0; j4 < 8; j4++){
                {
                    uint32_t b0, b1, b2, b3;
                    ldsm4(b0, b1, b2, b3, krow + ckK[0]);
                    mma168_z(acc[2 * j4],     qA[0], b0, b1);
                    mma168_z(acc[2 * j4 + 1], qA[0], b2, b3);
                }
                #pragma unroll
                for (int k = 1; k < 4; k++){
                    uint32_t b0, b1, b2, b3;
                    ldsm4(b0, b1, b2, b3, krow + ckK[k]);
                    mma168(acc[2 * j4],     qA[k], b0, b1);
                    mma168(acc[2 * j4 + 1], qA[k], b2, b3);
                }
                krow += 2048;
                mx1 = fmaxf(mx1, fmaxf(fmaxf(acc[2*j4][0], acc[2*j4][1]),
                                       fmaxf(acc[2*j4+1][0], acc[2*j4+1][1])));
                mx2 = fmaxf(mx2, fmaxf(fmaxf(acc[2*j4][2], acc[2*j4][3]),
                                       fmaxf(acc[2*j4+1][2], acc[2*j4+1][3])));
            }
        }
        mx1 = fmaxf(mx1, __shfl_xor_sync(0xffffffffu, mx1, 1));
        mx1 = fmaxf(mx1, __shfl_xor_sync(0xffffffffu, mx1, 2));
        mx2 = fmaxf(mx2, __shfl_xor_sync(0xffffffffu, mx2, 1));
        mx2 = fmaxf(mx2, __shfl_xor_sync(0xffffffffu, mx2, 2));

        const float nm1 = fmaxf(m1, mx1), nm2 = fmaxf(m2, mx2);
        const float adj1 = mx1 - 2.0f * nm1, adj2 = mx2 - 2.0f * nm2;
        // o is all zero; reference's o*=osc(0) is a no-op on zeros.
        #pragma unroll
        for (int t = 0; t < 16; t++){
            plA[t] = exp2_h2(acc[t][0], acc[t][1], adj1);
            phA[t] = exp2_h2(acc[t][2], acc[t][3], adj2);
        }
        m1 = nm1; m2 = nm2;

        asm volatile("cp.async.wait_group 0;" ::: "memory");
        __syncthreads();
    }

    // ---- main pipelined loop ----
    for (int kt = 1; kt < 31; kt += 2){
        fa_iter(kt,     sb, tid, gk, gv, qA, ckK, ckV, rbK, rbV, bone,
                o, m1, m2, plA, phA, plB, phB);
        fa_iter(kt + 1, sb, tid, gk, gv, qA, ckK, ckV, rbK, rbV, bone,
                o, m1, m2, plB, phB, plA, phA);
    }
    fa_iter(31, sb, tid, gk, gv, qA, ckK, ckV, rbK, rbV, bone,
            o, m1, m2, plA, phA, plB, phB);

    // ---- epilogue: final deferred MMA2(31); V(31) lives in buffer 31%3=1 ----
    {
        const uint32_t vrow = sb + VOFF + 1 * TILEB + rbV * 128;
        #pragma unroll
        for (int kk = 0; kk < 8; kk++)
            mma2_kk(o, vrow + kk * 2048, ckV, bone,
                    plB[2*kk], phB[2*kk], plB[2*kk+1], phB[2*kk+1]);
    }

    // ---- divide by ssum, write out ----
    float sum1 = __shfl_sync(0xffffffffu, o[8][0], lane & ~3);
    float sum2 = __shfl_sync(0xffffffffu, o[8][2], lane & ~3);
    const float inv1 = 1.0f / sum1, inv2 = 1.0f / sum2;

    const int r1 = 16 * w + (lane >> 2);
    float* Ob = O + ((size_t)bh * S_LEN + (size_t)qt * 64) * 64;
    #pragma unroll
    for (int t = 0; t < 8; t++){
        int col = 8 * t + (lane & 3) * 2;
        *(float2*)(Ob + (size_t)r1 * 64 + col) =
            make_float2(o[t][0] * inv1, o[t][1] * inv1);
        *(float2*)(Ob + (size_t)(r1 + 8) * 64 + col) =
            make_float2(o[t][2] * inv2, o[t][3] * inv2);
    }
}

extern "C" void kernel_launch(void* const* d_in, const int* in_sizes, int n_in,
                              void* d_out, int out_size)
{
    const float*  Q = (const float*)d_in[0];
    const float4* K = (const float4*)d_in[1];
    const float4* V = (const float4*)d_in[2];
    float* Ot = (float*)d_out;

    cudaFuncSetAttribute(fa_mma, cudaFuncAttributeMaxDynamicSharedMemorySize, SMEM_MAIN);
    cvt_pre<<<6144, 256>>>(K, V);
    fa_mma<<<BH_N * 64, 128, SMEM_MAIN>>>(Q, Ot);
}

// round 16
// speedup vs baseline: 1.0843x; 1.0843x over previous
#include <cuda_runtime.h>
#include <cuda_fp16.h>
#include <cstdint>

// FlashAttention B=4,H=12,S=4096,D=64, TILE=128, fp32 in/out.
// mma.sync m16n8k16 fp16 (plain sm_103 target — tcgen05 unavailable).
// Reference recurrence kept exactly: p = exp(s + mx - 2*nm),
// O = O*exp(m-nm) + P@V, ssum = ssum*exp(m-nm) + rowsum(P).
// Base-2 softmax domain (Q pre-scaled by 0.125*log2 e).
//
// R16: R13 (best passing config: 3 CTAs/SM, 128 thr, 64 q-rows, fp32-acc
// MMA1, KV-only pre-kernel, Q folded via cp.async) + phase stagger:
// co-resident CTAs sleep color*850ns (~1/3 iteration) before the main loop
// so their MMA / softmax phases anti-align instead of phase-locking,
// keeping the tensor pipe fed during other CTAs' softmax windows.

#define S_LEN 4096
#define NKT   32
#define BH_N  48

#define TILEB 16384
#define QOFF  0                       // 64 rows x 128B = 8KB (fp16 Q)
#define KOFF  8192
#define VOFF  (8192 + 2*16384)
#define VBUF1 (VOFF + 16384)          // Q fp32 staging pre-loop
#define SMEM_MAIN (8192 + 4*16384)    // 73728

#define QSCALE (0.125f * 1.44269504f)

__device__ __align__(128) __half g_Kh[(size_t)BH_N * S_LEN * 64];
__device__ __align__(128) __half g_Vh[(size_t)BH_N * S_LEN * 64];

// ---------------- pre-kernel: K,V fp32 -> fp16 ------------------------------
__global__ void __launch_bounds__(256) cvt_pre(const float4* __restrict__ K,
                                               const float4* __restrict__ V)
{
    const int PER = (int)((size_t)BH_N * S_LEN * 64 / 4);
    int gid = blockIdx.x * 256 + threadIdx.x;
    int stride = gridDim.x * 256;
    for (int i = gid; i < 2 * PER; i += stride) {
        int t = i / PER, off = i - t * PER;
        const float4* src = (t == 0) ? K : V;
        uint2* dst = (uint2*)((t == 0) ? g_Kh : g_Vh);
        float4 v = src[off];
        __half2 h0 = __floats2half2_rn(v.x, v.y);
        __half2 h1 = __floats2half2_rn(v.z, v.w);
        uint2 w;
        w.x = *(uint32_t*)&h0;
        w.y = *(uint32_t*)&h1;
        dst[off] = w;
    }
}

// ---------------- helpers ----------------
__device__ __forceinline__ uint32_t smem_u32(const void* p){
    uint32_t a; asm("{ .reg .u64 t; cvta.to.shared.u64 t, %1; cvt.u32.u64 %0, t; }"
                    : "=r"(a) : "l"(p)); return a;
}
__device__ __forceinline__ void cpa16(uint32_t dst, const void* src){
    asm volatile("cp.async.cg.shared.global [%0], [%1], 16;" :: "r"(dst), "l"(src));
}
__device__ __forceinline__ void ldsm4(uint32_t& r0, uint32_t& r1, uint32_t& r2,
                                      uint32_t& r3, uint32_t a){
    asm volatile("ldmatrix.sync.aligned.m8n8.x4.shared.b16 {%0,%1,%2,%3}, [%4];"
                 : "=r"(r0), "=r"(r1), "=r"(r2), "=r"(r3) : "r"(a));
}
__device__ __forceinline__ void ldsm4t(uint32_t& r0, uint32_t& r1, uint32_t& r2,
                                       uint32_t& r3, uint32_t a){
    asm volatile("ldmatrix.sync.aligned.m8n8.x4.trans.shared.b16 {%0,%1,%2,%3}, [%4];"
                 : "=r"(r0), "=r"(r1), "=r"(r2), "=r"(r3) : "r"(a));
}
__device__ __forceinline__ void mma168(float* d, const uint32_t* a,
                                       uint32_t b0, uint32_t b1){
    asm volatile(
        "mma.sync.aligned.m16n8k16.row.col.f32.f16.f16.f32 "
        "{%0,%1,%2,%3}, {%4,%5,%6,%7}, {%8,%9}, {%0,%1,%2,%3};"
        : "+f"(d[0]), "+f"(d[1]), "+f"(d[2]), "+f"(d[3])
        : "r"(a[0]), "r"(a[1]), "r"(a[2]), "r"(a[3]), "r"(b0), "r"(b1));
}
__device__ __forceinline__ void mma168_z(float* d, const uint32_t* a,
                                         uint32_t b0, uint32_t b1){
    asm volatile(
        "mma.sync.aligned.m16n8k16.row.col.f32.f16.f16.f32 "
        "{%0,%1,%2,%3}, {%4,%5,%6,%7}, {%8,%9}, {%10,%10,%10,%10};"
        : "=f"(d[0]), "=f"(d[1]), "=f"(d[2]), "=f"(d[3])
        : "r"(a[0]), "r"(a[1]), "r"(a[2]), "r"(a[3]), "r"(b0), "r"(b1),
          "f"(0.0f));
}
__device__ __forceinline__ uint32_t exp2_h2(float lo, float hi, float adj){
    __half2 h = __floats2half2_rn(lo + adj, hi + adj);
    h = h2exp2(h);
    return *(uint32_t*)&h;
}

// stage one K tile + one V tile (fp16, 16KB each), 128 threads, XOR swizzle
__device__ __forceinline__ void stage_kv(uint32_t sb, int buf, int tid,
                                         const __half* gk, const __half* gv){
    const int row0 = tid >> 3, c = tid & 7;
    const uint32_t sw = (uint32_t)((c ^ (row0 & 7)) << 4);
    uint32_t dk = sb + KOFF + buf * TILEB + row0 * 128 + sw;
    uint32_t dv = sb + VOFF + buf * TILEB + row0 * 128 + sw;
    const __half* sk = gk + row0 * 64 + c * 8;
    const __half* sv = gv + row0 * 64 + c * 8;
    #pragma unroll
    for (int i = 0; i < 8; i++){
        cpa16(dk, sk); dk += 2048; sk += 1024;
        cpa16(dv, sv); dv += 2048; sv += 1024;
    }
    asm volatile("cp.async.commit_group;" ::: "memory");
}

// ---------------- main kernel: 128 threads, 64 q-rows, 3 CTAs/SM ------------
__global__ void __launch_bounds__(128, 3)
fa_mma(const float* __restrict__ Qf, float* __restrict__ O)
{
    extern __shared__ char smraw[];
    const uint32_t sb = smem_u32(smraw);
    const int tid  = threadIdx.x;
    const int lane = tid & 31;
    const int w    = tid >> 5;
    const int bh   = blockIdx.x >> 6;
    const int qt   = blockIdx.x & 63;

    const float* gqf = Qf + ((size_t)bh * S_LEN + (size_t)qt * 64) * 64;
    const __half* gk = g_Kh + (size_t)bh * S_LEN * 64;
    const __half* gv = g_Vh + (size_t)bh * S_LEN * 64;

    const uint32_t xk = (uint32_t)(lane & 7) << 4;

    // ---- prologue: Q fp32 -> Vbuf1 (group 0), KV tile 0 (group 1) ----
    {
        uint32_t dq = sb + VBUF1 + tid * 16;
        const float* sq = gqf + tid * 4;
        #pragma unroll
        for (int i = 0; i < 8; i++){ cpa16(dq, sq); dq += 2048; sq += 512; }
        asm volatile("cp.async.commit_group;" ::: "memory");
    }
    stage_kv(sb, 0, tid, gk, gv);
    asm volatile("cp.async.wait_group 1;" ::: "memory");
    __syncthreads();

    // convert Q: smem fp32 -> smem fp16 (scaled, swizzled)
    {
        const int row = tid >> 1, hf = tid & 1;
        const uint32_t srcb = sb + VBUF1 + row * 256 + hf * 128;
        const uint32_t rowbase = sb + QOFF + row * 128;
        #pragma unroll
        for (int i = 0; i < 8; i++){
            uint32_t x0, x1, x2, x3;
            asm volatile("ld.shared.v4.b32 {%0,%1,%2,%3}, [%4];"
                         : "=r"(x0), "=r"(x1), "=r"(x2), "=r"(x3)
                         : "r"(srcb + i * 16));
            __half2 h0 = __floats2half2_rn(__uint_as_float(x0) * QSCALE,
                                           __uint_as_float(x1) * QSCALE);
            __half2 h1 = __floats2half2_rn(__uint_as_float(x2) * QSCALE,
                                           __uint_as_float(x3) * QSCALE);
            int c = hf * 4 + (i >> 1);
            uint32_t a = rowbase + ((uint32_t)(c ^ (row & 7)) << 4) + (i & 1) * 8;
            asm volatile("st.shared.v2.b32 [%0], {%1,%2};"
                         :: "r"(a), "r"(*(uint32_t*)&h0), "r"(*(uint32_t*)&h1));
        }
    }
    asm volatile("cp.async.wait_group 0;" ::: "memory");
    __syncthreads();

    // Q A-fragments (persist)
    uint32_t qA[4][4];
    {
        int qrow = 16 * w + (lane & 15);
        int qc   = lane >> 4;
        uint32_t qb = sb + QOFF + qrow * 128;
        #pragma unroll
        for (int k = 0; k < 4; k++)
            ldsm4(qA[k][0], qA[k][1], qA[k][2], qA[k][3],
                  qb + ((uint32_t)((2 * k + qc) << 4) ^ xk));
    }

    // ---- phase stagger: anti-align co-resident CTAs (bid, bid+148,
    // bid+296 -> distinct colors since 148 % 3 == 1). ~1/3 iteration each.
    {
        const unsigned color = blockIdx.x % 3u;
        if (color) __nanosleep(color * 850u);
    }

    const int rbK = (lane & 7) + ((lane >> 4) << 3);
    const int cbK = (lane >> 3) & 1;
    const int rbV = (lane & 7) + (((lane >> 3) & 1) << 3);
    const int cbV = lane >> 4;
    uint32_t ckK[4], ckV[4];
    #pragma unroll
    for (int k = 0; k < 4; k++){
        ckK[k] = ((uint32_t)((2 * k + cbK) << 4)) ^ xk;
        ckV[k] = ((uint32_t)((2 * k + cbV) << 4)) ^ xk;
    }
    const uint32_t bone = (lane < 4) ? 0x3C003C00u : 0u;

    float o[9][4];
    #pragma unroll
    for (int t = 0; t < 9; t++)
        #pragma unroll
        for (int c = 0; c < 4; c++) o[t][c] = 0.0f;
    float m1 = -INFINITY, m2 = -INFINITY;

    for (int kt = 0; kt < NKT; kt++){
        const int buf = kt & 1;
        if (kt + 1 < NKT)
            stage_kv(sb, buf ^ 1, tid, gk + (size_t)(kt + 1) * 8192,
                                       gv + (size_t)(kt + 1) * 8192);

        // ---- MMA1 (k=0 writes acc with C=0) + fused partial row-max ----
        float acc[16][4];
        float mx1 = -INFINITY, mx2 = -INFINITY;
        {
            uint32_t krow = sb + KOFF + buf * TILEB + rbK * 128;
            #pragma unroll
            for (int j4 = 0; j4 < 8; j4++){
                {
                    uint32_t b0, b1, b2, b3;
                    ldsm4(b0, b1, b2, b3, krow + ckK[0]);
                    mma168_z(acc[2 * j4],     qA[0], b0, b1);
                    mma168_z(acc[2 * j4 + 1], qA[0], b2, b3);
                }
                #pragma unroll
                for (int k = 1; k < 4; k++){
                    uint32_t b0, b1, b2, b3;
                    ldsm4(b0, b1, b2, b3, krow + ckK[k]);
                    mma168(acc[2 * j4],     qA[k], b0, b1);
                    mma168(acc[2 * j4 + 1], qA[k], b2, b3);
                }
                krow += 2048;
                mx1 = fmaxf(mx1, fmaxf(fmaxf(acc[2*j4][0], acc[2*j4][1]),
                                       fmaxf(acc[2*j4+1][0], acc[2*j4+1][1])));
                mx2 = fmaxf(mx2, fmaxf(fmaxf(acc[2*j4][2], acc[2*j4][3]),
                                       fmaxf(acc[2*j4+1][2], acc[2*j4+1][3])));
            }
        }

        mx1 = fmaxf(mx1, __shfl_xor_sync(0xffffffffu, mx1, 1));
        mx1 = fmaxf(mx1, __shfl_xor_sync(0xffffffffu, mx1, 2));
        mx2 = fmaxf(mx2, __shfl_xor_sync(0xffffffffu, mx2, 1));
        mx2 = fmaxf(mx2, __shfl_xor_sync(0xffffffffu, mx2, 2));

        const float nm1 = fmaxf(m1, mx1), nm2 = fmaxf(m2, mx2);
        const float adj1 = mx1 - 2.0f * nm1, adj2 = mx2 - 2.0f * nm2;
        const float osc1 = exp2f(m1 - nm1), osc2 = exp2f(m2 - nm2);

        if (__any_sync(0xffffffffu, (nm1 != m1) | (nm2 != m2))){
            #pragma unroll
            for (int t = 0; t < 9; t++){
                o[t][0] *= osc1; o[t][1] *= osc1;
                o[t][2] *= osc2; o[t][3] *= osc2;
            }
        }
        m1 = nm1; m2 = nm2;

        // ---- bulk P conversion (acc dies; pl/ph take its space) ----
        uint32_t pl[16], ph[16];
        #pragma unroll
        for (int t = 0; t < 16; t++){
            pl[t] = exp2_h2(acc[t][0], acc[t][1], adj1);
            ph[t] = exp2_h2(acc[t][2], acc[t][3], adj2);
        }

        // ---- MMA2: O += P @ V ; rowsum via constant ones B-fragment ----
        {
            uint32_t vrow = sb + VOFF + buf * TILEB + rbV * 128;
            #pragma unroll
            for (int kk = 0; kk < 8; kk++){
                uint32_t aA[4] = { pl[2*kk], ph[2*kk], pl[2*kk+1], ph[2*kk+1] };
                #pragma unroll
                for (int j4 = 0; j4 < 4; j4++){
                    uint32_t b0, b1, b2, b3;
                    ldsm4t(b0, b1, b2, b3, vrow + ckV[j4]);
                    mma168(o[2 * j4],     aA, b0, b1);
                    mma168(o[2 * j4 + 1], aA, b2, b3);
                }
                mma168(o[8], aA, bone, bone);
                vrow += 2048;
            }
        }

        asm volatile("cp.async.wait_group 0;" ::: "memory");
        __syncthreads();
    }

    // ---- epilogue ----
    float sum1 = __shfl_sync(0xffffffffu, o[8][0], lane & ~3);
    float sum2 = __shfl_sync(0xffffffffu, o[8][2], lane & ~3);
    const float inv1 = 1.0f / sum1, inv2 = 1.0f / sum2;

    const int r1 = 16 * w + (lane >> 2);
    float* Ob = O + ((size_t)bh * S_LEN + (size_t)qt * 64) * 64;
    #pragma unroll
    for (int t = 0; t < 8; t++){
        int col = 8 * t + (lane & 3) * 2;
        *(float2*)(Ob + (size_t)r1 * 64 + col) =
            make_float2(o[t][0] * inv1, o[t][1] * inv1);
        *(float2*)(Ob + (size_t)(r1 + 8) * 64 + col) =
            make_float2(o[t][2] * inv2, o[t][3] * inv2);
    }
}

extern "C" void kernel_launch(void* const* d_in, const int* in_sizes, int n_in,
                              void* d_out, int out_size)
{
    const float*  Q = (const float*)d_in[0];
    const float4* K = (const float4*)d_in[1];
    const float4* V = (const float4*)d_in[2];
    float* Ot = (float*)d_out;

    cudaFuncSetAttribute(fa_mma, cudaFuncAttributeMaxDynamicSharedMemorySize, SMEM_MAIN);
    cvt_pre<<<6144, 256>>>(K, V);
    fa_mma<<<BH_N * 64, 128, SMEM_MAIN>>>(Q, Ot);
}

// round 17
// speedup vs baseline: 1.0996x; 1.0141x over previous
#include <cuda_runtime.h>
#include <cuda_fp16.h>
#include <cstdint>

// FlashAttention B=4,H=12,S=4096,D=64, TILE=128, fp32 in/out.
// mma.sync m16n8k16 fp16 (plain sm_103 target — tcgen05 unavailable).
// Reference recurrence kept exactly: p = exp(s + mx - 2*nm),
// O = O*exp(m-nm) + P@V, ssum = ssum*exp(m-nm) + rowsum(P).
// Base-2 softmax domain (Q pre-scaled by 0.125*log2 e).
//
// R17: R13 + 4-chain MMA1. The old MMA1 inner loop had only 2 accumulator
// chains with asm-volatile ordering -> one warp supplies <= 2 HMMA per RAW
// latency (~1/12 per cyc) < pipe rate (1/8): a lone warp cannot saturate
// the tensor pipe. Interleaving pairs of j4 strips gives 4 chains
// (same-acc distance ~32+ cyc >= latency) so each warp self-saturates.

#define S_LEN 4096
#define NKT   32
#define BH_N  48

#define TILEB 16384
#define QOFF  0                       // 64 rows x 128B = 8KB (fp16 Q)
#define KOFF  8192
#define VOFF  (8192 + 2*16384)
#define VBUF1 (VOFF + 16384)          // Q fp32 staging pre-loop
#define SMEM_MAIN (8192 + 4*16384)    // 73728

#define QSCALE (0.125f * 1.44269504f)

__device__ __align__(128) __half g_Kh[(size_t)BH_N * S_LEN * 64];
__device__ __align__(128) __half g_Vh[(size_t)BH_N * S_LEN * 64];

// ---------------- pre-kernel: K,V fp32 -> fp16 ------------------------------
__global__ void __launch_bounds__(256) cvt_pre(const float4* __restrict__ K,
                                               const float4* __restrict__ V)
{
    const int PER = (int)((size_t)BH_N * S_LEN * 64 / 4);
    int gid = blockIdx.x * 256 + threadIdx.x;
    int stride = gridDim.x * 256;
    for (int i = gid; i < 2 * PER; i += stride) {
        int t = i / PER, off = i - t * PER;
        const float4* src = (t == 0) ? K : V;
        uint2* dst = (uint2*)((t == 0) ? g_Kh : g_Vh);
        float4 v = src[off];
        __half2 h0 = __floats2half2_rn(v.x, v.y);
        __half2 h1 = __floats2half2_rn(v.z, v.w);
        uint2 w;
        w.x = *(uint32_t*)&h0;
        w.y = *(uint32_t*)&h1;
        dst[off] = w;
    }
}

// ---------------- helpers ----------------
__device__ __forceinline__ uint32_t smem_u32(const void* p){
    uint32_t a; asm("{ .reg .u64 t; cvta.to.shared.u64 t, %1; cvt.u32.u64 %0, t; }"
                    : "=r"(a) : "l"(p)); return a;
}
__device__ __forceinline__ void cpa16(uint32_t dst, const void* src){
    asm volatile("cp.async.cg.shared.global [%0], [%1], 16;" :: "r"(dst), "l"(src));
}
__device__ __forceinline__ void ldsm4(uint32_t& r0, uint32_t& r1, uint32_t& r2,
                                      uint32_t& r3, uint32_t a){
    asm volatile("ldmatrix.sync.aligned.m8n8.x4.shared.b16 {%0,%1,%2,%3}, [%4];"
                 : "=r"(r0), "=r"(r1), "=r"(r2), "=r"(r3) : "r"(a));
}
__device__ __forceinline__ void ldsm4t(uint32_t& r0, uint32_t& r1, uint32_t& r2,
                                       uint32_t& r3, uint32_t a){
    asm volatile("ldmatrix.sync.aligned.m8n8.x4.trans.shared.b16 {%0,%1,%2,%3}, [%4];"
                 : "=r"(r0), "=r"(r1), "=r"(r2), "=r"(r3) : "r"(a));
}
__device__ __forceinline__ void mma168(float* d, const uint32_t* a,
                                       uint32_t b0, uint32_t b1){
    asm volatile(
        "mma.sync.aligned.m16n8k16.row.col.f32.f16.f16.f32 "
        "{%0,%1,%2,%3}, {%4,%5,%6,%7}, {%8,%9}, {%0,%1,%2,%3};"
        : "+f"(d[0]), "+f"(d[1]), "+f"(d[2]), "+f"(d[3])
        : "r"(a[0]), "r"(a[1]), "r"(a[2]), "r"(a[3]), "r"(b0), "r"(b1));
}
__device__ __forceinline__ void mma168_z(float* d, const uint32_t* a,
                                         uint32_t b0, uint32_t b1){
    asm volatile(
        "mma.sync.aligned.m16n8k16.row.col.f32.f16.f16.f32 "
        "{%0,%1,%2,%3}, {%4,%5,%6,%7}, {%8,%9}, {%10,%10,%10,%10};"
        : "=f"(d[0]), "=f"(d[1]), "=f"(d[2]), "=f"(d[3])
        : "r"(a[0]), "r"(a[1]), "r"(a[2]), "r"(a[3]), "r"(b0), "r"(b1),
          "f"(0.0f));
}
__device__ __forceinline__ uint32_t exp2_h2(float lo, float hi, float adj){
    __half2 h = __floats2half2_rn(lo + adj, hi + adj);
    h = h2exp2(h);
    return *(uint32_t*)&h;
}

// stage one K tile + one V tile (fp16, 16KB each), 128 threads, XOR swizzle
__device__ __forceinline__ void stage_kv(uint32_t sb, int buf, int tid,
                                         const __half* gk, const __half* gv){
    const int row0 = tid >> 3, c = tid & 7;
    const uint32_t sw = (uint32_t)((c ^ (row0 & 7)) << 4);
    uint32_t dk = sb + KOFF + buf * TILEB + row0 * 128 + sw;
    uint32_t dv = sb + VOFF + buf * TILEB + row0 * 128 + sw;
    const __half* sk = gk + row0 * 64 + c * 8;
    const __half* sv = gv + row0 * 64 + c * 8;
    #pragma unroll
    for (int i = 0; i < 8; i++){
        cpa16(dk, sk); dk += 2048; sk += 1024;
        cpa16(dv, sv); dv += 2048; sv += 1024;
    }
    asm volatile("cp.async.commit_group;" ::: "memory");
}

// ---------------- main kernel: 128 threads, 64 q-rows, 3 CTAs/SM ------------
__global__ void __launch_bounds__(128, 3)
fa_mma(const float* __restrict__ Qf, float* __restrict__ O)
{
    extern __shared__ char smraw[];
    const uint32_t sb = smem_u32(smraw);
    const int tid  = threadIdx.x;
    const int lane = tid & 31;
    const int w    = tid >> 5;
    const int bh   = blockIdx.x >> 6;
    const int qt   = blockIdx.x & 63;

    const float* gqf = Qf + ((size_t)bh * S_LEN + (size_t)qt * 64) * 64;
    const __half* gk = g_Kh + (size_t)bh * S_LEN * 64;
    const __half* gv = g_Vh + (size_t)bh * S_LEN * 64;

    const uint32_t xk = (uint32_t)(lane & 7) << 4;

    // ---- prologue: Q fp32 -> Vbuf1 (group 0), KV tile 0 (group 1) ----
    {
        uint32_t dq = sb + VBUF1 + tid * 16;
        const float* sq = gqf + tid * 4;
        #pragma unroll
        for (int i = 0; i < 8; i++){ cpa16(dq, sq); dq += 2048; sq += 512; }
        asm volatile("cp.async.commit_group;" ::: "memory");
    }
    stage_kv(sb, 0, tid, gk, gv);
    asm volatile("cp.async.wait_group 1;" ::: "memory");
    __syncthreads();

    // convert Q: smem fp32 -> smem fp16 (scaled, swizzled)
    {
        const int row = tid >> 1, hf = tid & 1;
        const uint32_t srcb = sb + VBUF1 + row * 256 + hf * 128;
        const uint32_t rowbase = sb + QOFF + row * 128;
        #pragma unroll
        for (int i = 0; i < 8; i++){
            uint32_t x0, x1, x2, x3;
            asm volatile("ld.shared.v4.b32 {%0,%1,%2,%3}, [%4];"
                         : "=r"(x0), "=r"(x1), "=r"(x2), "=r"(x3)
                         : "r"(srcb + i * 16));
            __half2 h0 = __floats2half2_rn(__uint_as_float(x0) * QSCALE,
                                           __uint_as_float(x1) * QSCALE);
            __half2 h1 = __floats2half2_rn(__uint_as_float(x2) * QSCALE,
                                           __uint_as_float(x3) * QSCALE);
            int c = hf * 4 + (i >> 1);
            uint32_t a = rowbase + ((uint32_t)(c ^ (row & 7)) << 4) + (i & 1) * 8;
            asm volatile("st.shared.v2.b32 [%0], {%1,%2};"
                         :: "r"(a), "r"(*(uint32_t*)&h0), "r"(*(uint32_t*)&h1));
        }
    }
    asm volatile("cp.async.wait_group 0;" ::: "memory");
    __syncthreads();

    // Q A-fragments (persist)
    uint32_t qA[4][4];
    {
        int qrow = 16 * w + (lane & 15);
        int qc   = lane >> 4;
        uint32_t qb = sb + QOFF + qrow * 128;
        #pragma unroll
        for (int k = 0; k < 4; k++)
            ldsm4(qA[k][0], qA[k][1], qA[k][2], qA[k][3],
                  qb + ((uint32_t)((2 * k + qc) << 4) ^ xk));
    }

    const int rbK = (lane & 7) + ((lane >> 4) << 3);
    const int cbK = (lane >> 3) & 1;
    const int rbV = (lane & 7) + (((lane >> 3) & 1) << 3);
    const int cbV = lane >> 4;
    uint32_t ckK[4], ckV[4];
    #pragma unroll
    for (int k = 0; k < 4; k++){
        ckK[k] = ((uint32_t)((2 * k + cbK) << 4)) ^ xk;
        ckV[k] = ((uint32_t)((2 * k + cbV) << 4)) ^ xk;
    }
    const uint32_t bone = (lane < 4) ? 0x3C003C00u : 0u;

    float o[9][4];
    #pragma unroll
    for (int t = 0; t < 9; t++)
        #pragma unroll
        for (int c = 0; c < 4; c++) o[t][c] = 0.0f;
    float m1 = -INFINITY, m2 = -INFINITY;

    for (int kt = 0; kt < NKT; kt++){
        const int buf = kt & 1;
        if (kt + 1 < NKT)
            stage_kv(sb, buf ^ 1, tid, gk + (size_t)(kt + 1) * 8192,
                                       gv + (size_t)(kt + 1) * 8192);

        // ---- MMA1: j4 strips in pairs -> 4 accumulator chains in flight ----
        float acc[16][4];
        float mx1 = -INFINITY, mx2 = -INFINITY;
        {
            uint32_t krowA = sb + KOFF + buf * TILEB + rbK * 128;
            #pragma unroll
            for (int jp = 0; jp < 4; jp++){
                const uint32_t krowB = krowA + 2048;
                // k = 0: zero-C writes on all 4 chains
                {
                    uint32_t a0, a1, a2, a3, c0, c1, c2, c3;
                    ldsm4(a0, a1, a2, a3, krowA + ckK[0]);
                    ldsm4(c0, c1, c2, c3, krowB + ckK[0]);
                    mma168_z(acc[4*jp],     qA[0], a0, a1);
                    mma168_z(acc[4*jp+2],   qA[0], c0, c1);
                    mma168_z(acc[4*jp+1],   qA[0], a2, a3);
                    mma168_z(acc[4*jp+3],   qA[0], c2, c3);
                }
                #pragma unroll
                for (int k = 1; k < 4; k++){
                    uint32_t a0, a1, a2, a3, c0, c1, c2, c3;
                    ldsm4(a0, a1, a2, a3, krowA + ckK[k]);
                    ldsm4(c0, c1, c2, c3, krowB + ckK[k]);
                    mma168(acc[4*jp],     qA[k], a0, a1);
                    mma168(acc[4*jp+2],   qA[k], c0, c1);
                    mma168(acc[4*jp+1],   qA[k], a2, a3);
                    mma168(acc[4*jp+3],   qA[k], c2, c3);
                }
                krowA += 4096;
                // partial row-max over the 4 tiles just finished (exact: max assoc.)
                mx1 = fmaxf(mx1, fmaxf(
                        fmaxf(fmaxf(acc[4*jp][0],   acc[4*jp][1]),
                              fmaxf(acc[4*jp+1][0], acc[4*jp+1][1])),
                        fmaxf(fmaxf(acc[4*jp+2][0], acc[4*jp+2][1]),
                              fmaxf(acc[4*jp+3][0], acc[4*jp+3][1]))));
                mx2 = fmaxf(mx2, fmaxf(
                        fmaxf(fmaxf(acc[4*jp][2],   acc[4*jp][3]),
                              fmaxf(acc[4*jp+1][2], acc[4*jp+1][3])),
                        fmaxf(fmaxf(acc[4*jp+2][2], acc[4*jp+2][3]),
                              fmaxf(acc[4*jp+3][2], acc[4*jp+3][3]))));
            }
        }

        mx1 = fmaxf(mx1, __shfl_xor_sync(0xffffffffu, mx1, 1));
        mx1 = fmaxf(mx1, __shfl_xor_sync(0xffffffffu, mx1, 2));
        mx2 = fmaxf(mx2, __shfl_xor_sync(0xffffffffu, mx2, 1));
        mx2 = fmaxf(mx2, __shfl_xor_sync(0xffffffffu, mx2, 2));

        const float nm1 = fmaxf(m1, mx1), nm2 = fmaxf(m2, mx2);
        const float adj1 = mx1 - 2.0f * nm1, adj2 = mx2 - 2.0f * nm2;
        const float osc1 = exp2f(m1 - nm1), osc2 = exp2f(m2 - nm2);

        if (__any_sync(0xffffffffu, (nm1 != m1) | (nm2 != m2))){
            #pragma unroll
            for (int t = 0; t < 9; t++){
                o[t][0] *= osc1; o[t][1] *= osc1;
                o[t][2] *= osc2; o[t][3] *= osc2;
            }
        }
        m1 = nm1; m2 = nm2;

        // ---- bulk P conversion (acc dies; pl/ph take its space) ----
        uint32_t pl[16], ph[16];
        #pragma unroll
        for (int t = 0; t < 16; t++){
            pl[t] = exp2_h2(acc[t][0], acc[t][1], adj1);
            ph[t] = exp2_h2(acc[t][2], acc[t][3], adj2);
        }

        // ---- MMA2: O += P @ V ; rowsum via constant ones B-fragment ----
        {
            uint32_t vrow = sb + VOFF + buf * TILEB + rbV * 128;
            #pragma unroll
            for (int kk = 0; kk < 8; kk++){
                uint32_t aA[4] = { pl[2*kk], ph[2*kk], pl[2*kk+1], ph[2*kk+1] };
                #pragma unroll
                for (int j4 = 0; j4 < 4; j4++){
                    uint32_t b0, b1, b2, b3;
                    ldsm4t(b0, b1, b2, b3, vrow + ckV[j4]);
                    mma168(o[2 * j4],     aA, b0, b1);
                    mma168(o[2 * j4 + 1], aA, b2, b3);
                }
                mma168(o[8], aA, bone, bone);
                vrow += 2048;
            }
        }

        asm volatile("cp.async.wait_group 0;" ::: "memory");
        __syncthreads();
    }

    // ---- epilogue ----
    float sum1 = __shfl_sync(0xffffffffu, o[8][0], lane & ~3);
    float sum2 = __shfl_sync(0xffffffffu, o[8][2], lane & ~3);
    const float inv1 = 1.0f / sum1, inv2 = 1.0f / sum2;

    const int r1 = 16 * w + (lane >> 2);
    float* Ob = O + ((size_t)bh * S_LEN + (size_t)qt * 64) * 64;
    #pragma unroll
    for (int t = 0; t < 8; t++){
        int col = 8 * t + (lane & 3) * 2;
        *(float2*)(Ob + (size_t)r1 * 64 + col) =
            make_float2(o[t][0] * inv1, o[t][1] * inv1);
        *(float2*)(Ob + (size_t)(r1 + 8) * 64 + col) =
            make_float2(o[t][2] * inv2, o[t][3] * inv2);
    }
}

extern "C" void kernel_launch(void* const* d_in, const int* in_sizes, int n_in,
                              void* d_out, int out_size)
{
    const float*  Q = (const float*)d_in[0];
    const float4* K = (const float4*)d_in[1];
    const float4* V = (const float4*)d_in[2];
    float* Ot = (float*)d_out;

    cudaFuncSetAttribute(fa_mma, cudaFuncAttributeMaxDynamicSharedMemorySize, SMEM_MAIN);
    cvt_pre<<<6144, 256>>>(K, V);
    fa_mma<<<BH_N * 64, 128, SMEM_MAIN>>>(Q, Ot);
}